// round 7
// baseline (speedup 1.0000x reference)
#include <cuda_runtime.h>
#include <cuda_fp16.h>
#include <cstdint>

// Problem dims
#define BATCH 8
#define SEQ   2048
#define KDIM  4096
#define MDIM  4096
#define NDIM  (BATCH * SEQ)     // 16384
#define NCHUNK (KDIM / 32)      // 128 k32-chunks per row

// GEMM tiling: CTA 128x256x64, 8 warps (2m x 4n), warp 64x64
#define BM 128
#define BN 256
#define BK 64
#define NST 4
#define GTHREADS 256
#define KITERS (KDIM / BK)      // 64

// Stage layout: A-compressed 8KB @0, meta 1KB @8192, B 32KB @9216
#define META_OFF    8192
#define B_OFF       9216
#define STAGE_BYTES 41984       // 41*1024
#define SMEM_TOTAL  (NST * STAGE_BYTES)   // 167936

#define MAX_EXTRA 32
#define CT_STRIDE 260           // Ctile padded stride (floats)

// Device scratch
__device__ __align__(16) __half   g_Wc[(size_t)MDIM * KDIM / 2];    // 16 MB 2:4 values
__device__ __align__(16) uint32_t g_meta[(size_t)MDIM * NCHUNK];    // 2 MB row-major meta
__device__ __align__(16) uint32_t g_metaP[(size_t)MDIM * NCHUNK];   // 2 MB lane-packed meta
__device__ __align__(16) __half   g_Xh[(size_t)NDIM * KDIM];        // 128 MB
__device__ __align__(16) __half   g_XT[(size_t)KDIM * NDIM];        // 128 MB transposed
__device__ int   g_ecnt[MDIM];
__device__ float g_ew[MDIM][MAX_EXTRA];
__device__ int   g_ek[MDIM][MAX_EXTRA];

// ---------------------------------------------------------------------------
__global__ void zero_ecnt() {
    int i = blockIdx.x * blockDim.x + threadIdx.x;
    if (i < MDIM) g_ecnt[i] = 0;
}

// ---------------------------------------------------------------------------
// Compress W*mask into 2:4 values + row-major metadata + exact-extras list.
// ---------------------------------------------------------------------------
__global__ void compress_w(const float* __restrict__ w,
                           const int* __restrict__ mask) {
    int id = blockIdx.x * blockDim.x + threadIdx.x;
    if (id >= MDIM * NCHUNK) return;
    int m = id / NCHUNK, c = id % NCHUNK;

    float wv[32];
    int   mv[32];
    const float4* wp = reinterpret_cast<const float4*>(w + (size_t)m * KDIM + c * 32);
    const int4*   mp = reinterpret_cast<const int4*>(mask + (size_t)m * KDIM + c * 32);
#pragma unroll
    for (int q = 0; q < 8; q++) {
        float4 a = wp[q];  int4 b = mp[q];
        wv[4*q+0]=a.x; wv[4*q+1]=a.y; wv[4*q+2]=a.z; wv[4*q+3]=a.w;
        mv[4*q+0]=b.x; mv[4*q+1]=b.y; mv[4*q+2]=b.z; mv[4*q+3]=b.w;
    }

    __half vals[16];
    uint32_t meta = 0;
#pragma unroll
    for (int g = 0; g < 8; g++) {
        int idx[4], n = 0;
        float v[4];
#pragma unroll
        for (int j = 0; j < 4; j++)
            if (mv[4*g+j]) { idx[n] = j; v[n] = wv[4*g+j]; n++; }
        int i0, i1; float v0, v1;
        if (n == 0)      { i0 = 0; i1 = 3; v0 = 0.0f; v1 = 0.0f; }
        else if (n == 1) {
            if (idx[0] == 3) { i0 = 0; i1 = 3; v0 = 0.0f; v1 = v[0]; }
            else             { i0 = idx[0]; i1 = 3; v0 = v[0]; v1 = 0.0f; }
        } else           { i0 = idx[0]; i1 = idx[1]; v0 = v[0]; v1 = v[1]; }
        meta |= (uint32_t)(i0 | (i1 << 2)) << (4 * g);
        vals[2*g]   = __float2half(v0);
        vals[2*g+1] = __float2half(v1);
        for (int e = 2; e < n; e++) {
            int slot = atomicAdd(&g_ecnt[m], 1);
            if (slot < MAX_EXTRA) {
                g_ek[m][slot] = c * 32 + 4 * g + idx[e];
                g_ew[m][slot] = v[e];
            }
        }
    }
    uint4* dst = reinterpret_cast<uint4*>(&g_Wc[(size_t)m * (KDIM/2) + c * 16]);
    dst[0] = reinterpret_cast<uint4*>(vals)[0];
    dst[1] = reinterpret_cast<uint4*>(vals)[1];
    g_meta[(size_t)m * NCHUNK + c] = meta;
}

// ---------------------------------------------------------------------------
// Repack metadata to per-lane L3 words.
// For each 16-row m-tile, chunk, pair c (0..7), t (0..1):
//   word(p = c*2+t) = (meta[row c] >> 16t & 0xFFFF) | (meta[row c+8] >> 16t & 0xFFFF) << 16
// Lane 4c+t of the consuming quad loads word p = c*2+t directly.
// ---------------------------------------------------------------------------
__global__ void repack_meta() {
    int id = blockIdx.x * blockDim.x + threadIdx.x;       // over 256*128*16
    if (id >= (MDIM / 16) * NCHUNK * 16) return;
    int p     = id & 15;
    int chunk = (id >> 4) % NCHUNK;
    int mt    = id / (16 * NCHUNK);
    int c = p >> 1, t = p & 1;
    uint32_t lo = (g_meta[(size_t)(mt * 16 + c)     * NCHUNK + chunk] >> (16 * t)) & 0xFFFF;
    uint32_t hi = (g_meta[(size_t)(mt * 16 + c + 8) * NCHUNK + chunk] >> (16 * t)) & 0xFFFF;
    g_metaP[((size_t)mt * NCHUNK + chunk) * 16 + p] = lo | (hi << 16);
}

// ---------------------------------------------------------------------------
// x -> fp16 (straight) + fp16 transposed copy XT[k][n]
// ---------------------------------------------------------------------------
__global__ void convert_x_t(const float* __restrict__ x) {
    __shared__ __half tile[64][72];
    int k0 = blockIdx.x * 64;
    int n0 = blockIdx.y * 64;
    int t = threadIdx.x;
#pragma unroll
    for (int j = 0; j < 16; j++) {
        int idx = t + j * 256;
        int nn = idx >> 6, kk = idx & 63;
        __half h = __float2half(x[(size_t)(n0 + nn) * KDIM + k0 + kk]);
        g_Xh[(size_t)(n0 + nn) * KDIM + k0 + kk] = h;
        tile[nn][kk] = h;
    }
    __syncthreads();
#pragma unroll
    for (int j = 0; j < 16; j++) {
        int idx = t + j * 256;
        int kk = idx >> 6, nn = idx & 63;
        g_XT[(size_t)(k0 + kk) * NDIM + n0 + nn] = tile[nn][kk];
    }
}

// ---------------------------------------------------------------------------
// Helpers
// ---------------------------------------------------------------------------
__device__ __forceinline__ uint32_t smem_u32(const void* p) {
    uint32_t a;
    asm("{ .reg .u64 t; cvta.to.shared.u64 t, %1; cvt.u32.u64 %0, t; }"
        : "=r"(a) : "l"(p));
    return a;
}

__device__ __forceinline__ void ldsm_x4(uint32_t& r0, uint32_t& r1,
                                        uint32_t& r2, uint32_t& r3,
                                        uint32_t addr) {
    asm volatile("ldmatrix.sync.aligned.m8n8.x4.shared.b16 {%0,%1,%2,%3}, [%4];"
                 : "=r"(r0), "=r"(r1), "=r"(r2), "=r"(r3) : "r"(addr));
}

__device__ __forceinline__ void mmasp(float* c, const uint32_t* a,
                                      uint32_t b0, uint32_t b1,
                                      uint32_t b2, uint32_t b3, uint32_t e) {
    asm volatile(
        "mma.sp::ordered_metadata.sync.aligned.m16n8k32.row.col.f32.f16.f16.f32 "
        "{%0,%1,%2,%3}, {%4,%5,%6,%7}, {%8,%9,%10,%11}, {%0,%1,%2,%3}, %12, 0x0;"
        : "+f"(c[0]), "+f"(c[1]), "+f"(c[2]), "+f"(c[3])
        : "r"(a[0]), "r"(a[1]), "r"(a[2]), "r"(a[3]),
          "r"(b0), "r"(b1), "r"(b2), "r"(b3), "r"(e));
}

// ---------------------------------------------------------------------------
// Producer. Meta: 256 packed words/stage, linear layout
// w = mtl*32 + chunk*16 + p  (mtl = local 16-row tile 0..7, chunk 0..1).
// ---------------------------------------------------------------------------
__device__ __forceinline__ void produce(uint32_t stage, int tid, int j,
                                        int mBase, int nBase) {
    const __half* bseg = &g_Xh[(size_t)nBase * KDIM + j * BK];
#pragma unroll
    for (int t = 0; t < 8; t++) {
        int id = tid + t * GTHREADS;          // 0..2047
        int row = id >> 3, c = id & 7;
        const __half* src = bseg + (size_t)row * KDIM + c * 8;
        uint32_t off = row * 128 + c * 16;
        uint32_t dst = stage + B_OFF + (off ^ ((off >> 3) & 0x70));
        asm volatile("cp.async.cg.shared.global [%0], [%1], 16;"
                     :: "r"(dst), "l"(src) : "memory");
    }
    const __half* aseg = &g_Wc[(size_t)mBase * (KDIM / 2) + j * 32];
#pragma unroll
    for (int t = 0; t < 2; t++) {
        int id = tid + t * GTHREADS;          // 0..511
        int row = id >> 2, c = id & 3;
        const __half* src = aseg + (size_t)row * (KDIM / 2) + c * 8;
        uint32_t off = row * 64 + c * 16;
        uint32_t dst = stage + (off ^ ((off >> 3) & 0x30));
        asm volatile("cp.async.cg.shared.global [%0], [%1], 16;"
                     :: "r"(dst), "l"(src) : "memory");
    }
    if (tid < 128) {
        int w0 = 2 * tid;                     // words w0, w0+1 (same mtl/chunk)
        int mtl = w0 >> 5;
        int chunk = (w0 >> 4) & 1;
        int p = w0 & 15;
        const uint32_t* src =
            &g_metaP[((size_t)(mBase / 16 + mtl) * NCHUNK + (j * 2 + chunk)) * 16 + p];
        uint32_t dst = stage + META_OFF + tid * 8;
        asm volatile("cp.async.ca.shared.global [%0], [%1], 8;"
                     :: "r"(dst), "l"(src) : "memory");
    }
}

// ---------------------------------------------------------------------------
// Sparse GEMM + fused exact correction
// ---------------------------------------------------------------------------
__global__ void __launch_bounds__(GTHREADS, 1)
gemm_sp(float* __restrict__ out) {
    extern __shared__ __align__(1024) char smem[];
    const uint32_t sb = smem_u32(smem);
    const int tid = threadIdx.x;
    const int lane = tid & 31;
    const int wid = tid >> 5;
    const int wm = wid >> 2;          // 0..1
    const int wn = wid & 3;           // 0..3

    const int mBase = blockIdx.x * BM;
    const int nBase = blockIdx.y * BN;

    const int aRowL = wm * 64 + (lane & 15);
    const uint32_t aColL = (uint32_t)((lane >> 4) << 4);
    const int bRowL = wn * 64 + (lane & 7) + ((lane >> 4) << 3);
    const uint32_t bColL = (uint32_t)(((lane >> 3) & 1) << 4);
    // Packed-meta byte offset within (mtile, chunk) block: p*4 = c*8 + t*4
    const uint32_t metaLane = (uint32_t)(((lane >> 2) << 3) + ((lane & 1) << 2));

    float acc[4][8][4];
#pragma unroll
    for (int i = 0; i < 4; i++)
#pragma unroll
        for (int j = 0; j < 8; j++)
#pragma unroll
            for (int r = 0; r < 4; r++) acc[i][j][r] = 0.0f;

    produce(sb + 0 * STAGE_BYTES, tid, 0, mBase, nBase);
    asm volatile("cp.async.commit_group;" ::: "memory");
    produce(sb + 1 * STAGE_BYTES, tid, 1, mBase, nBase);
    asm volatile("cp.async.commit_group;" ::: "memory");
    produce(sb + 2 * STAGE_BYTES, tid, 2, mBase, nBase);
    asm volatile("cp.async.commit_group;" ::: "memory");

    for (int i = 0; i < KITERS; i++) {
        asm volatile("cp.async.wait_group 2;" ::: "memory");
        __syncthreads();

        if (i + 3 < KITERS)
            produce(sb + ((i + 3) % NST) * STAGE_BYTES, tid, i + 3, mBase, nBase);
        asm volatile("cp.async.commit_group;" ::: "memory");

        const uint32_t stA = sb + (i % NST) * STAGE_BYTES;
        const uint32_t stM = stA + META_OFF;
        const uint32_t stB = stA + B_OFF;

#pragma unroll
        for (int kk = 0; kk < 2; kk++) {
            uint32_t a[4][4], b[4][8], mt_meta[4];
#pragma unroll
            for (int mt = 0; mt < 4; mt++) {
                uint32_t off = (uint32_t)(aRowL + mt * 16) * 64 + aColL + kk * 32;
                ldsm_x4(a[mt][0], a[mt][1], a[mt][2], a[mt][3],
                        stA + (off ^ ((off >> 3) & 0x30)));
                // meta word for this lane: block (wm*4+mt, kk), offset metaLane
                asm volatile("ld.shared.b32 %0, [%1];"
                             : "=r"(mt_meta[mt])
                             : "r"(stM + (uint32_t)(wm * 4 + mt) * 128 + kk * 64 + metaLane));
            }
#pragma unroll
            for (int nt = 0; nt < 4; nt++) {
                uint32_t off0 = (uint32_t)(bRowL + nt * 16) * 128 + bColL + kk * 64;
                ldsm_x4(b[nt][0], b[nt][1], b[nt][2], b[nt][3],
                        stB + (off0 ^ ((off0 >> 3) & 0x70)));
                uint32_t off1 = off0 + 32;
                ldsm_x4(b[nt][4], b[nt][5], b[nt][6], b[nt][7],
                        stB + (off1 ^ ((off1 >> 3) & 0x70)));
            }
#pragma unroll
            for (int mt = 0; mt < 4; mt++)
#pragma unroll
                for (int nt = 0; nt < 4; nt++) {
                    mmasp(acc[mt][2 * nt],     a[mt],
                          b[nt][0], b[nt][1], b[nt][4], b[nt][5], mt_meta[mt]);
                    mmasp(acc[mt][2 * nt + 1], a[mt],
                          b[nt][2], b[nt][3], b[nt][6], b[nt][7], mt_meta[mt]);
                }
        }
    }

    asm volatile("cp.async.wait_group 0;" ::: "memory");
    __syncthreads();

    // Correction tile: extras applied exactly (fp32)
    float* Ct = reinterpret_cast<float*>(smem);   // [128][CT_STRIDE]
#pragma unroll 1
    for (int r = 0; r < 16; r++) {
        int mLoc = wid * 16 + r;
        int m = mBase + mLoc;
        int cnt = g_ecnt[m];
        cnt = cnt < MAX_EXTRA ? cnt : MAX_EXTRA;
        float av[8] = {0, 0, 0, 0, 0, 0, 0, 0};
        for (int e = 0; e < cnt; e++) {
            int k = g_ek[m][e];
            float wv = g_ew[m][e];
            uint4 pk = *reinterpret_cast<const uint4*>(
                &g_XT[(size_t)k * NDIM + nBase + lane * 8]);
            const __half2* hp = reinterpret_cast<const __half2*>(&pk);
#pragma unroll
            for (int q = 0; q < 4; q++) {
                float2 f = __half22float2(hp[q]);
                av[2 * q]     += wv * f.x;
                av[2 * q + 1] += wv * f.y;
            }
        }
#pragma unroll
        for (int q = 0; q < 8; q++)
            Ct[mLoc * CT_STRIDE + lane * 8 + q] = av[q];
    }
    __syncthreads();

    const int b2 = nBase / SEQ;
    const int s0 = nBase % SEQ;
    const int mW = mBase + wm * 64;
    const int nW = s0 + wn * 64;
    const int rl = lane >> 2;
    const int cl = (lane & 3) * 2;
#pragma unroll
    for (int mt = 0; mt < 4; mt++) {
#pragma unroll
        for (int j = 0; j < 8; j++) {
            int mL0 = wm * 64 + mt * 16 + rl;
            int nL  = wn * 64 + j * 8 + cl;
            size_t base = ((size_t)b2 * MDIM + mW + mt * 16 + rl) * SEQ + nW + j * 8 + cl;
            *reinterpret_cast<float2*>(&out[base]) =
                make_float2(acc[mt][j][0] + Ct[mL0 * CT_STRIDE + nL],
                            acc[mt][j][1] + Ct[mL0 * CT_STRIDE + nL + 1]);
            *reinterpret_cast<float2*>(&out[base + 8 * SEQ]) =
                make_float2(acc[mt][j][2] + Ct[(mL0 + 8) * CT_STRIDE + nL],
                            acc[mt][j][3] + Ct[(mL0 + 8) * CT_STRIDE + nL + 1]);
        }
    }
}

// ---------------------------------------------------------------------------
// Launch
// ---------------------------------------------------------------------------
extern "C" void kernel_launch(void* const* d_in, const int* in_sizes, int n_in,
                              void* d_out, int out_size) {
    const float* x    = (const float*)d_in[0];   // [B, S, K]
    const float* w    = (const float*)d_in[1];   // [M, K]
    const int*   mask = (const int*)d_in[2];     // [M, K] bool -> int32
    float* out = (float*)d_out;                  // [B, M, S]

    zero_ecnt<<<16, 256>>>();
    compress_w<<<MDIM * NCHUNK / 256, 256>>>(w, mask);
    repack_meta<<<(MDIM / 16) * NCHUNK * 16 / 256, 256>>>();
    convert_x_t<<<dim3(KDIM / 64, NDIM / 64), 256>>>(x);

    cudaFuncSetAttribute(gemm_sp,
                         cudaFuncAttributeMaxDynamicSharedMemorySize, SMEM_TOTAL);
    dim3 grid(MDIM / BM, NDIM / BN);   // (32, 64): m fastest -> W panels L2-resident
    gemm_sp<<<grid, GTHREADS, SMEM_TOTAL>>>(out);
}

// round 8
// speedup vs baseline: 1.1276x; 1.1276x over previous
#include <cuda_runtime.h>
#include <cuda_fp16.h>
#include <cstdint>

// Problem dims
#define BATCH 8
#define SEQ   2048
#define KDIM  4096
#define MDIM  4096
#define NDIM  (BATCH * SEQ)   // 16384

// GEMM tiling: CTA 128x256x64, 16 warps (4m x 4n), warp tile 32x64
#define BM 128
#define BN 256
#define BK 64
#define NST 4
#define GTHREADS 512
#define KITERS (KDIM / BK)    // 64

#define A_BYTES (BM * 128)                 // 16384
#define B_BYTES (BN * 128)                 // 32768
#define STAGE_BYTES (A_BYTES + B_BYTES)    // 49152
#define SMEM_TOTAL (NST * STAGE_BYTES)     // 196608

// fp16 scratch
__device__ __align__(16) __half g_Wh[(size_t)MDIM * KDIM];   // 32 MB
__device__ __align__(16) __half g_Xh[(size_t)NDIM * KDIM];   // 128 MB

// ---------------------------------------------------------------------------
// Conversion kernels
// ---------------------------------------------------------------------------
__global__ void convert_w_kernel(const float* __restrict__ w,
                                 const int* __restrict__ mask) {
    size_t total4 = (size_t)MDIM * KDIM / 4;
    for (size_t i = (size_t)blockIdx.x * blockDim.x + threadIdx.x;
         i < total4; i += (size_t)gridDim.x * blockDim.x) {
        float4 wv = reinterpret_cast<const float4*>(w)[i];
        int4   mv = reinterpret_cast<const int4*>(mask)[i];
        float a = mv.x ? wv.x : 0.0f;
        float b = mv.y ? wv.y : 0.0f;
        float c = mv.z ? wv.z : 0.0f;
        float d = mv.w ? wv.w : 0.0f;
        __half2* o = reinterpret_cast<__half2*>(&g_Wh[i * 4]);
        o[0] = __floats2half2_rn(a, b);
        o[1] = __floats2half2_rn(c, d);
    }
}

__global__ void convert_x_kernel(const float* __restrict__ x) {
    size_t total4 = (size_t)NDIM * KDIM / 4;
    for (size_t i = (size_t)blockIdx.x * blockDim.x + threadIdx.x;
         i < total4; i += (size_t)gridDim.x * blockDim.x) {
        float4 xv = reinterpret_cast<const float4*>(x)[i];
        __half2* o = reinterpret_cast<__half2*>(&g_Xh[i * 4]);
        o[0] = __floats2half2_rn(xv.x, xv.y);
        o[1] = __floats2half2_rn(xv.z, xv.w);
    }
}

// ---------------------------------------------------------------------------
// Helpers
// ---------------------------------------------------------------------------
__device__ __forceinline__ uint32_t smem_u32(const void* p) {
    uint32_t a;
    asm("{ .reg .u64 t; cvta.to.shared.u64 t, %1; cvt.u32.u64 %0, t; }"
        : "=r"(a) : "l"(p));
    return a;
}

__device__ __forceinline__ void ldsm_x4(uint32_t& r0, uint32_t& r1,
                                        uint32_t& r2, uint32_t& r3,
                                        uint32_t addr) {
    asm volatile("ldmatrix.sync.aligned.m8n8.x4.shared.b16 {%0,%1,%2,%3}, [%4];"
                 : "=r"(r0), "=r"(r1), "=r"(r2), "=r"(r3) : "r"(addr));
}

__device__ __forceinline__ void mma16816(float* c, const uint32_t* a,
                                         uint32_t b0, uint32_t b1) {
    asm volatile(
        "mma.sync.aligned.m16n8k16.row.col.f32.f16.f16.f32 "
        "{%0,%1,%2,%3}, {%4,%5,%6,%7}, {%8,%9}, {%0,%1,%2,%3};"
        : "+f"(c[0]), "+f"(c[1]), "+f"(c[2]), "+f"(c[3])
        : "r"(a[0]), "r"(a[1]), "r"(a[2]), "r"(a[3]), "r"(b0), "r"(b1));
}

// ---------------------------------------------------------------------------
// Producer: 3072 x 16B cp.async per stage (A 1024, B 2048), 6 per thread.
// ---------------------------------------------------------------------------
__device__ __forceinline__ void produce(uint32_t stage, int tid, int j,
                                        int mBase, int nBase) {
    const __half* aseg = &g_Wh[(size_t)mBase * KDIM + j * BK];
    const __half* bseg = &g_Xh[(size_t)nBase * KDIM + j * BK];
#pragma unroll
    for (int t = 0; t < 6; t++) {
        int id = tid + t * GTHREADS;          // 0..3071
        int isB = (id >= 1024);
        int lid = isB ? (id - 1024) : id;
        int row = lid >> 3;
        int c   = lid & 7;
        const __half* src = (isB ? bseg : aseg) + (size_t)row * KDIM + c * 8;
        uint32_t off = row * 128 + c * 16;
        uint32_t dst = stage + (isB ? A_BYTES : 0) + (off ^ ((off >> 3) & 0x70));
        asm volatile("cp.async.cg.shared.global [%0], [%1], 16;"
                     :: "r"(dst), "l"(src) : "memory");
    }
}

// ---------------------------------------------------------------------------
// GEMM: C[m,n] = sum_k Wh[m,k] * Xh[n,k]; 16 warps = 4 per SMSP for latency cover
// ---------------------------------------------------------------------------
__global__ void __launch_bounds__(GTHREADS, 1)
gemm_hmma(float* __restrict__ out) {
    extern __shared__ __align__(1024) char smem[];
    const uint32_t sb = smem_u32(smem);
    const int tid = threadIdx.x;
    const int lane = tid & 31;
    const int wid = tid >> 5;
    const int wm = wid >> 2;          // 0..3  (m offset wm*32)
    const int wn = wid & 3;           // 0..3  (n offset wn*64)

    const int mBase = blockIdx.x * BM;
    const int nBase = blockIdx.y * BN;

    // Per-lane ldmatrix offsets
    const int aRow = wm * 32 + (lane & 15);
    const uint32_t aOff0 = (uint32_t)aRow * 128 + ((lane >> 4) << 4);
    const uint32_t aMask = ((((uint32_t)aRow * 128) >> 3) & 0x70);
    const int bRow = wn * 64 + (lane & 7) + ((lane >> 4) << 3);
    const uint32_t bOff0 = (uint32_t)bRow * 128 + (((lane >> 3) & 1) << 4);
    const uint32_t bMask = ((((uint32_t)bRow * 128) >> 3) & 0x70);

    float acc[2][8][4];
#pragma unroll
    for (int i = 0; i < 2; i++)
#pragma unroll
        for (int j = 0; j < 8; j++)
#pragma unroll
            for (int r = 0; r < 4; r++) acc[i][j][r] = 0.0f;

    produce(sb + 0 * STAGE_BYTES, tid, 0, mBase, nBase);
    asm volatile("cp.async.commit_group;" ::: "memory");
    produce(sb + 1 * STAGE_BYTES, tid, 1, mBase, nBase);
    asm volatile("cp.async.commit_group;" ::: "memory");
    produce(sb + 2 * STAGE_BYTES, tid, 2, mBase, nBase);
    asm volatile("cp.async.commit_group;" ::: "memory");

    for (int i = 0; i < KITERS; i++) {
        asm volatile("cp.async.wait_group 2;" ::: "memory");
        __syncthreads();

        if (i + 3 < KITERS)
            produce(sb + ((i + 3) % NST) * STAGE_BYTES, tid, i + 3, mBase, nBase);
        asm volatile("cp.async.commit_group;" ::: "memory");

        const uint32_t stA = sb + (i % NST) * STAGE_BYTES;
        const uint32_t stB = stA + A_BYTES;

#pragma unroll
        for (int kk = 0; kk < 4; kk++) {
            uint32_t a[2][4], b[4][4];
#pragma unroll
            for (int mt = 0; mt < 2; mt++) {
                uint32_t off = aOff0 + (uint32_t)mt * 16 * 128 + kk * 32;
                ldsm_x4(a[mt][0], a[mt][1], a[mt][2], a[mt][3],
                        stA + (off ^ aMask));
            }
#pragma unroll
            for (int nt = 0; nt < 4; nt++) {
                uint32_t off = bOff0 + (uint32_t)nt * 16 * 128 + kk * 32;
                ldsm_x4(b[nt][0], b[nt][1], b[nt][2], b[nt][3],
                        stB + (off ^ bMask));
            }
#pragma unroll
            for (int mt = 0; mt < 2; mt++)
#pragma unroll
                for (int nt = 0; nt < 4; nt++) {
                    mma16816(acc[mt][2 * nt],     a[mt], b[nt][0], b[nt][1]);
                    mma16816(acc[mt][2 * nt + 1], a[mt], b[nt][2], b[nt][3]);
                }
        }
    }

    // Epilogue: direct stores; each 4-lane group writes a full 32B sector.
    const int b2 = nBase / SEQ;
    const int s0 = nBase % SEQ;
    const int mW = mBase + wm * 32;
    const int nW = s0 + wn * 64;
    const int rl = lane >> 2;
    const int cl = (lane & 3) * 2;
#pragma unroll
    for (int mt = 0; mt < 2; mt++) {
#pragma unroll
        for (int j = 0; j < 8; j++) {
            size_t base = ((size_t)b2 * MDIM + mW + mt * 16 + rl) * SEQ + nW + j * 8 + cl;
            *reinterpret_cast<float2*>(&out[base]) =
                make_float2(acc[mt][j][0], acc[mt][j][1]);
            *reinterpret_cast<float2*>(&out[base + 8 * SEQ]) =
                make_float2(acc[mt][j][2], acc[mt][j][3]);
        }
    }
}

// ---------------------------------------------------------------------------
// Launch
// ---------------------------------------------------------------------------
extern "C" void kernel_launch(void* const* d_in, const int* in_sizes, int n_in,
                              void* d_out, int out_size) {
    const float* x    = (const float*)d_in[0];   // [B, S, K]
    const float* w    = (const float*)d_in[1];   // [M, K]
    const int*   mask = (const int*)d_in[2];     // [M, K] bool -> int32
    float* out = (float*)d_out;                  // [B, M, S]

    convert_w_kernel<<<2048, 256>>>(w, mask);
    convert_x_kernel<<<8192, 256>>>(x);

    cudaFuncSetAttribute(gemm_hmma,
                         cudaFuncAttributeMaxDynamicSharedMemorySize, SMEM_TOTAL);
    dim3 grid(MDIM / BM, NDIM / BN);   // (32, 64): m fastest -> W stays in L2
    gemm_hmma<<<grid, GTHREADS, SMEM_TOTAL>>>(out);
}